// round 1
// baseline (speedup 1.0000x reference)
#include <cuda_runtime.h>
#include <math.h>

// Problem constants (fixed by setup_inputs)
#define N_FEAT 131072
#define D      128
#define K      1024
#define TM     128
#define TN     128
#define DCH    16
#define NTHREADS 256
#define NBLOCKS  (N_FEAT / TM)

// Scratch (device globals; no allocation allowed)
__device__ float g_cnormT[D * K];     // normalized centers, transposed [d][k]
__device__ float g_cnorm[K];          // |c_k|
__device__ float g_cnormsq[K];        // |c_k|^2
__device__ float g_rinv[N_FEAT];      // 1 / max(|f_n|, eps)
__device__ float g_partial[NBLOCKS];  // per-block loss partial sums

// Packed f32x2 helpers (Blackwell sm_100+)
#define FMA2(acc_, a_, b_) \
    asm("fma.rn.f32x2 %0, %1, %2, %0;" : "+l"(acc_) : "l"(a_), "l"(b_))
#define PACK_DUP(out_, x_) \
    asm("mov.b64 %0, {%1, %1};" : "=l"(out_) : "r"(__float_as_uint(x_)))

// ---------------------------------------------------------------------------
// Normalize centers; store transposed for coalesced B-tile loads.
// ---------------------------------------------------------------------------
__global__ void prep_centers(const float* __restrict__ centers) {
    int k = blockIdx.x;
    int d = threadIdx.x;  // 128 threads
    float v = centers[k * D + d];
    float s = v * v;
    #pragma unroll
    for (int o = 16; o; o >>= 1) s += __shfl_down_sync(0xffffffffu, s, o);
    __shared__ float ws[4];
    if ((d & 31) == 0) ws[d >> 5] = s;
    __syncthreads();
    float tot  = ws[0] + ws[1] + ws[2] + ws[3];
    float norm = sqrtf(tot);
    float rinv = 1.0f / fmaxf(norm, 1e-12f);
    g_cnormT[d * K + k] = v * rinv;
    if (d == 0) { g_cnorm[k] = norm; g_cnormsq[k] = tot; }
}

// ---------------------------------------------------------------------------
// Per-feature inverse norms (one warp per row).
// ---------------------------------------------------------------------------
__global__ void prep_rnorm(const float* __restrict__ features) {
    int warp = (blockIdx.x * blockDim.x + threadIdx.x) >> 5;
    int lane = threadIdx.x & 31;
    if (warp >= N_FEAT) return;
    float4 v = ((const float4*)features)[(size_t)warp * (D / 4) + lane];
    float s = v.x * v.x + v.y * v.y + v.z * v.z + v.w * v.w;
    #pragma unroll
    for (int o = 16; o; o >>= 1) s += __shfl_down_sync(0xffffffffu, s, o);
    if (lane == 0) g_rinv[warp] = 1.0f / fmaxf(sqrtf(s), 1e-12f);
}

// ---------------------------------------------------------------------------
// Fused sims-GEMM + row argmax + loss partial.
// Block: 128 rows x all 1024 centers, 256 threads, 8x8 micro-tile (f32x2).
// ---------------------------------------------------------------------------
__global__ __launch_bounds__(NTHREADS, 2)
void gemm_argmax(const float* __restrict__ features) {
    __shared__ __align__(16) float As[DCH][TM + 4];  // [d][row], 528B rows
    __shared__ __align__(16) float Bs[DCH][TN + 4];  // [d][col]
    __shared__ float red_s[TM * 16];
    __shared__ int   red_i[TM * 16];
    __shared__ float lsum[TM];

    const int tid = threadIdx.x;
    const int tx  = tid & 15;
    const int ty  = tid >> 4;
    const int row0 = blockIdx.x * TM;

    // Hoisted A-load geometry (constant across dc/tile)
    const int rA0 = tid >> 2;                 // row for l=0
    const int rA1 = (tid + NTHREADS) >> 2;    // row for l=1
    const int dA0 = (tid & 3) * 4;
    const float ri0 = g_rinv[row0 + rA0];
    const float ri1 = g_rinv[row0 + rA1];
    const float* fbase0 = features + (size_t)(row0 + rA0) * D + dA0;
    const float* fbase1 = features + (size_t)(row0 + rA1) * D + dA0;

    const int ddB0 = tid >> 5;                // B-load geometry
    const int ddB1 = (tid + NTHREADS) >> 5;
    const int kB   = (tid & 31) * 4;

    float best[8];
    int   bidx[8];
    #pragma unroll
    for (int i = 0; i < 8; i++) { best[i] = -1e30f; bidx[i] = 0; }

    for (int tile = 0; tile < K / TN; tile++) {
        unsigned long long acc[8][4];
        #pragma unroll
        for (int i = 0; i < 8; i++)
            #pragma unroll
            for (int j = 0; j < 4; j++) acc[i][j] = 0ull;

        for (int dc = 0; dc < D / DCH; dc++) {
            // Stage A chunk (scaled by row inv-norm), transposed into smem
            {
                float4 v0 = *(const float4*)(fbase0 + dc * DCH);
                As[dA0 + 0][rA0] = v0.x * ri0; As[dA0 + 1][rA0] = v0.y * ri0;
                As[dA0 + 2][rA0] = v0.z * ri0; As[dA0 + 3][rA0] = v0.w * ri0;
                float4 v1 = *(const float4*)(fbase1 + dc * DCH);
                As[dA0 + 0][rA1] = v1.x * ri1; As[dA0 + 1][rA1] = v1.y * ri1;
                As[dA0 + 2][rA1] = v1.z * ri1; As[dA0 + 3][rA1] = v1.w * ri1;
            }
            // Stage B chunk (already transposed in global)
            {
                float4 w0 = *(const float4*)&g_cnormT[(dc * DCH + ddB0) * K + tile * TN + kB];
                *(float4*)&Bs[ddB0][kB] = w0;
                float4 w1 = *(const float4*)&g_cnormT[(dc * DCH + ddB1) * K + tile * TN + kB];
                *(float4*)&Bs[ddB1][kB] = w1;
            }
            __syncthreads();

            #pragma unroll
            for (int d = 0; d < DCH; d++) {
                float4 a0 = *(const float4*)&As[d][ty * 8];
                float4 a1 = *(const float4*)&As[d][ty * 8 + 4];
                ulonglong2 b0 = *(const ulonglong2*)&Bs[d][tx * 8];
                ulonglong2 b1 = *(const ulonglong2*)&Bs[d][tx * 8 + 4];
                unsigned long long bp[4] = {b0.x, b0.y, b1.x, b1.y};
                unsigned long long ap[8];
                PACK_DUP(ap[0], a0.x); PACK_DUP(ap[1], a0.y);
                PACK_DUP(ap[2], a0.z); PACK_DUP(ap[3], a0.w);
                PACK_DUP(ap[4], a1.x); PACK_DUP(ap[5], a1.y);
                PACK_DUP(ap[6], a1.z); PACK_DUP(ap[7], a1.w);
                #pragma unroll
                for (int i = 0; i < 8; i++)
                    #pragma unroll
                    for (int j = 0; j < 4; j++)
                        FMA2(acc[i][j], ap[i], bp[j]);
            }
            __syncthreads();
        }

        // Fold this tile into the running argmax (ascending k, strict >)
        #pragma unroll
        for (int i = 0; i < 8; i++) {
            #pragma unroll
            for (int j = 0; j < 4; j++) {
                float lo = __uint_as_float((unsigned)(acc[i][j] & 0xffffffffull));
                float hi = __uint_as_float((unsigned)(acc[i][j] >> 32));
                int kb = tile * TN + tx * 8 + j * 2;
                if (lo > best[i]) { best[i] = lo; bidx[i] = kb; }
                if (hi > best[i]) { best[i] = hi; bidx[i] = kb + 1; }
            }
        }
    }

    // Cross-thread per-row argmax (ascending tx = ascending k)
    __syncthreads();
    #pragma unroll
    for (int i = 0; i < 8; i++) {
        red_s[(ty * 8 + i) * 16 + tx] = best[i];
        red_i[(ty * 8 + i) * 16 + tx] = bidx[i];
    }
    __syncthreads();
    if (tid < TM) {
        float bs = -1e30f; int bk = 0;
        #pragma unroll
        for (int t = 0; t < 16; t++) {
            float s = red_s[tid * 16 + t];
            if (s > bs) { bs = s; bk = red_i[tid * 16 + t]; }
        }
        // ||f_norm - c||^2 = 1 + |c|^2 - 2 |c| sim
        lsum[tid] = 1.0f + g_cnormsq[bk] - 2.0f * g_cnorm[bk] * bs;
    }
    __syncthreads();
    #pragma unroll
    for (int s = TM / 2; s > 0; s >>= 1) {
        if (tid < s) lsum[tid] += lsum[tid + s];
        __syncthreads();
    }
    if (tid == 0) g_partial[blockIdx.x] = lsum[0];
}

// ---------------------------------------------------------------------------
// Deterministic final reduction (double accumulation).
// ---------------------------------------------------------------------------
__global__ void finalize(float* __restrict__ out) {
    __shared__ double sd[256];
    double s = 0.0;
    for (int i = threadIdx.x; i < NBLOCKS; i += 256) s += (double)g_partial[i];
    sd[threadIdx.x] = s;
    __syncthreads();
    for (int st = 128; st > 0; st >>= 1) {
        if (threadIdx.x < st) sd[threadIdx.x] += sd[threadIdx.x + st];
        __syncthreads();
    }
    if (threadIdx.x == 0) out[0] = (float)(sd[0] / (double)N_FEAT);
}

extern "C" void kernel_launch(void* const* d_in, const int* in_sizes, int n_in,
                              void* d_out, int out_size) {
    const float* features = (const float*)d_in[0];
    const float* centers  = (const float*)d_in[1];
    float* out = (float*)d_out;

    prep_centers<<<K, D>>>(centers);
    prep_rnorm<<<N_FEAT / 8, 256>>>(features);   // 8 warps/block, 1 row/warp
    gemm_argmax<<<NBLOCKS, NTHREADS>>>(features);
    finalize<<<1, 256>>>(out);
}

// round 5
// speedup vs baseline: 3.7179x; 3.7179x over previous
#include <cuda_runtime.h>
#include <cuda_bf16.h>
#include <cstdint>
#include <math.h>

// ---------------------------------------------------------------------------
// Problem constants
// ---------------------------------------------------------------------------
#define N_FEAT 131072
#define D      128
#define K      1024
#define TM     128            // rows per CTA
#define TN     128            // centers per B-tile
#define NTILE  (K / TN)       // 8
#define KD2    256            // split K-dim [hi|lo] (A) / [hi|hi] (B)
#define NBLK   (N_FEAT / TM)  // 1024

#define A_TILE_BYTES (TM * KD2 * 2)   // 65536
#define B_TILE_BYTES (TN * KD2 * 2)   // 65536

// SMEM map (dynamic)
#define SM_MBAR 0
#define SM_A    1024
#define SM_B0   (SM_A + A_TILE_BYTES)
#define SM_B1   (SM_B0 + B_TILE_BYTES)
#define SMEM_TOTAL (SM_B1 + B_TILE_BYTES)   // 197632
// epilogue scratch lives in the (dead) B region; A region stays live
#define SM_REDS SM_B0
#define SM_REDI (SM_B0 + 8192)
#define SM_LSUM (SM_B0 + 16384)

#define MB_A  0
#define MB_B0 8
#define MB_B1 16

// ---------------------------------------------------------------------------
// Device scratch
// ---------------------------------------------------------------------------
__device__ __align__(1024) unsigned char g_A[(size_t)NBLK * A_TILE_BYTES]; // 64 MB
__device__ __align__(1024) unsigned char g_B[NTILE * B_TILE_BYTES];        // 512 KB
__device__ float g_cnormsq[K];
__device__ float g_partial[NBLK];

// ---------------------------------------------------------------------------
// PTX helpers (all legal on non-'a' sm_103 target)
// ---------------------------------------------------------------------------
__device__ __forceinline__ uint32_t smem_u32(const void* p) {
    uint32_t a;
    asm("{ .reg .u64 t; cvta.to.shared.u64 t, %1; cvt.u32.u64 %0, t; }" : "=r"(a) : "l"(p));
    return a;
}
#define MBAR_INIT(a, c) \
    asm volatile("mbarrier.init.shared.b64 [%0], %1;" :: "r"((uint32_t)(a)), "r"((uint32_t)(c)) : "memory")
#define MBAR_EXPECT_TX(a, b) \
    asm volatile("mbarrier.arrive.expect_tx.shared.b64 _, [%0], %1;" :: "r"((uint32_t)(a)), "r"((uint32_t)(b)) : "memory")
#define MBAR_WAIT(a, ph) do { \
    uint32_t _m = (uint32_t)(a), _p = (uint32_t)(ph), _d; \
    asm volatile("{ .reg .pred p; mbarrier.try_wait.parity.acquire.cta.shared::cta.b64 p, [%1], %2; selp.b32 %0,1,0,p; }" \
        : "=r"(_d) : "r"(_m), "r"(_p) : "memory"); \
    if (!_d) { \
        asm volatile("{ .reg .pred P1; WL%=: mbarrier.try_wait.parity.acquire.cta.shared::cta.b64 P1, [%0], %1, 0x989680; @P1 bra.uni WD%=; bra.uni WL%=; WD%=: }" \
            :: "r"(_m), "r"(_p) : "memory"); \
    } \
} while (0)

__device__ __forceinline__ void bulk_g2s(uint32_t dst, const void* src,
                                         uint32_t bytes, uint32_t mbar) {
    asm volatile(
        "cp.async.bulk.shared::cta.global.mbarrier::complete_tx::bytes [%0], [%1], %2, [%3];"
        :: "r"(dst), "l"(src), "r"(bytes), "r"(mbar) : "memory");
}
#define LDSM_X4(r, a) \
    asm volatile("ldmatrix.sync.aligned.m8n8.x4.shared.b16 {%0,%1,%2,%3}, [%4];" \
        : "=r"((r)[0]), "=r"((r)[1]), "=r"((r)[2]), "=r"((r)[3]) : "r"(a))
#define MMA_BF16(c, a, b0_, b1_) \
    asm volatile("mma.sync.aligned.m16n8k16.row.col.f32.bf16.bf16.f32 " \
        "{%0,%1,%2,%3}, {%4,%5,%6,%7}, {%8,%9}, {%0,%1,%2,%3};" \
        : "+f"((c)[0]), "+f"((c)[1]), "+f"((c)[2]), "+f"((c)[3]) \
        : "r"((a)[0]), "r"((a)[1]), "r"((a)[2]), "r"((a)[3]), "r"(b0_), "r"(b1_))

// Swizzled byte offset inside a [128 x 256] bf16 tile: 512 B/row, 16B chunks
__device__ __host__ __forceinline__ uint32_t tile_off(int rr, int d) {
    return (uint32_t)(rr * 512 + (((d >> 3) ^ (rr & 7)) << 4) + (d & 7) * 2);
}
__device__ __forceinline__ unsigned short bf16_bits(__nv_bfloat16 h) {
    return *reinterpret_cast<unsigned short*>(&h);
}
__device__ __forceinline__ float bfb2f(unsigned int bits16) {
    return __uint_as_float(bits16 << 16);
}

// ---------------------------------------------------------------------------
// Prep: centers -> normalize; hi(bf16) replicated into BOTH K-halves of g_B
// ---------------------------------------------------------------------------
__global__ void prep_centers(const float* __restrict__ centers) {
    int k = blockIdx.x;
    int d = threadIdx.x;  // 128
    float v = centers[k * D + d];
    float s = v * v;
    #pragma unroll
    for (int o = 16; o; o >>= 1) s += __shfl_down_sync(0xffffffffu, s, o);
    __shared__ float ws[4];
    if ((d & 31) == 0) ws[d >> 5] = s;
    __syncthreads();
    float tot  = ws[0] + ws[1] + ws[2] + ws[3];
    float norm = sqrtf(tot);
    float x = v / fmaxf(norm, 1e-12f);
    unsigned short hb = bf16_bits(__float2bfloat16(x));
    unsigned char* tile = g_B + (size_t)(k >> 7) * B_TILE_BYTES;
    int nn = k & 127;
    *(unsigned short*)(tile + tile_off(nn, d))       = hb;
    *(unsigned short*)(tile + tile_off(nn, d + 128)) = hb;
    if (d == 0) g_cnormsq[k] = tot;
}

// ---------------------------------------------------------------------------
// Prep: features -> normalize, hi/lo split into g_A tiles
// ---------------------------------------------------------------------------
__global__ void prep_features(const float* __restrict__ features) {
    int row  = blockIdx.x * 8 + (threadIdx.x >> 5);
    int lane = threadIdx.x & 31;
    float4 v = ((const float4*)features)[(size_t)row * (D / 4) + lane];
    float s = v.x * v.x + v.y * v.y + v.z * v.z + v.w * v.w;
    #pragma unroll
    for (int o = 16; o; o >>= 1) s += __shfl_xor_sync(0xffffffffu, s, o);
    float rinv = 1.0f / fmaxf(sqrtf(s), 1e-12f);

    float x[4] = {v.x * rinv, v.y * rinv, v.z * rinv, v.w * rinv};
    unsigned int hp[2], lp[2];
    #pragma unroll
    for (int e = 0; e < 2; e++) {
        __nv_bfloat16 h0 = __float2bfloat16(x[2 * e]);
        __nv_bfloat16 h1 = __float2bfloat16(x[2 * e + 1]);
        __nv_bfloat16 l0 = __float2bfloat16(x[2 * e]     - __bfloat162float(h0));
        __nv_bfloat16 l1 = __float2bfloat16(x[2 * e + 1] - __bfloat162float(h1));
        hp[e] = (unsigned)bf16_bits(h0) | ((unsigned)bf16_bits(h1) << 16);
        lp[e] = (unsigned)bf16_bits(l0) | ((unsigned)bf16_bits(l1) << 16);
    }
    unsigned char* tile = g_A + (size_t)(row >> 7) * A_TILE_BYTES;
    int rr = row & 127;
    int d2 = lane * 4;
    *(uint2*)(tile + tile_off(rr, d2))       = make_uint2(hp[0], hp[1]);
    *(uint2*)(tile + tile_off(rr, d2 + 128)) = make_uint2(lp[0], lp[1]);
}

// ---------------------------------------------------------------------------
// Main: mma.sync bf16 GEMM + fused argmax + EXACT loss epilogue
// 8 warps: warp_m = wid>>2 (2), warp_n = wid&3 (4); warp tile 64x32
// ---------------------------------------------------------------------------
__global__ __launch_bounds__(256, 1)
void gemm_argmax_mma(const float* __restrict__ centers) {
    extern __shared__ __align__(1024) unsigned char smem[];
    uint32_t sb = smem_u32(smem);
    const int tid = threadIdx.x;
    const int wid = tid >> 5, l = tid & 31;
    const int warp_m = wid >> 2, warp_n = wid & 3;

    if (tid == 0) {
        MBAR_INIT(sb + SM_MBAR + MB_A, 1);
        MBAR_INIT(sb + SM_MBAR + MB_B0, 1);
        MBAR_INIT(sb + SM_MBAR + MB_B1, 1);
    }
    __syncthreads();
    if (tid == 0) {
        MBAR_EXPECT_TX(sb + SM_MBAR + MB_A, A_TILE_BYTES);
        bulk_g2s(sb + SM_A, g_A + (size_t)blockIdx.x * A_TILE_BYTES,
                 A_TILE_BYTES, sb + SM_MBAR + MB_A);
        MBAR_EXPECT_TX(sb + SM_MBAR + MB_B0, B_TILE_BYTES);
        bulk_g2s(sb + SM_B0, g_B, B_TILE_BYTES, sb + SM_MBAR + MB_B0);
    }

    // ldmatrix lane geometry.
    // A (x4): groups -> (rows r0-7,k0-7)(rows+8,k0-7)(rows0-7,k8-15)(rows+8,k8-15)
    const int a_row_in = (l & 7) + ((l >> 3) & 1) * 8;
    const int a_cb     = (l >> 4);
    // B (x4, NON-trans; B stored [n][k], k contiguous):
    // groups -> (n0-7,k0-7)(n0-7,k8-15)(n8-15,k0-7)(n8-15,k8-15)
    // => r0=b0/r1=b1 for n-oct 0, r2=b0/r3=b1 for n-oct 1
    const int b_row_in = (l & 7) + ((l >> 4) & 1) * 8;
    const int b_cb     = (l >> 3) & 1;

    float best[8];
    int   bidx[8];
    #pragma unroll
    for (int i = 0; i < 8; i++) { best[i] = -1e30f; bidx[i] = 0; }

    MBAR_WAIT(sb + SM_MBAR + MB_A, 0);

    for (int t = 0; t < NTILE; t++) {
        const uint32_t bbuf = (t & 1) ? (sb + SM_B1) : (sb + SM_B0);
        MBAR_WAIT(sb + SM_MBAR + ((t & 1) ? MB_B1 : MB_B0), (t >> 1) & 1);
        if (tid == 0 && t + 1 < NTILE) {
            uint32_t mb = sb + SM_MBAR + (((t + 1) & 1) ? MB_B1 : MB_B0);
            MBAR_EXPECT_TX(mb, B_TILE_BYTES);
            bulk_g2s(((t + 1) & 1) ? (sb + SM_B1) : (sb + SM_B0),
                     g_B + (size_t)(t + 1) * B_TILE_BYTES, B_TILE_BYTES, mb);
        }

        float acc[4][4][4];
        #pragma unroll
        for (int mi = 0; mi < 4; mi++)
            #pragma unroll
            for (int ni = 0; ni < 4; ni++)
                #pragma unroll
                for (int e = 0; e < 4; e++) acc[mi][ni][e] = 0.0f;

        #pragma unroll
        for (int kk = 0; kk < 16; kk++) {
            uint32_t af[4][4];
            #pragma unroll
            for (int mi = 0; mi < 4; mi++) {
                int row = warp_m * 64 + mi * 16 + a_row_in;
                uint32_t addr = sb + SM_A + row * 512 +
                                (((kk * 2 + a_cb) ^ (row & 7)) << 4);
                LDSM_X4(af[mi], addr);
            }
            uint32_t bfm[2][4];
            #pragma unroll
            for (int bp = 0; bp < 2; bp++) {
                int nrow = warp_n * 32 + bp * 16 + b_row_in;
                uint32_t addr = bbuf + nrow * 512 +
                                (((kk * 2 + b_cb) ^ (nrow & 7)) << 4);
                LDSM_X4(bfm[bp], addr);
            }
            #pragma unroll
            for (int mi = 0; mi < 4; mi++)
                #pragma unroll
                for (int ni = 0; ni < 4; ni++)
                    MMA_BF16(acc[mi][ni], af[mi],
                             bfm[ni >> 1][(ni & 1) * 2], bfm[ni >> 1][(ni & 1) * 2 + 1]);
        }

        #pragma unroll
        for (int mi = 0; mi < 4; mi++) {
            #pragma unroll
            for (int ni = 0; ni < 4; ni++) {
                int k0 = t * TN + warp_n * 32 + ni * 8 + (l & 3) * 2;
                float c0 = acc[mi][ni][0], c1 = acc[mi][ni][1];
                float c2 = acc[mi][ni][2], c3 = acc[mi][ni][3];
                int i0 = mi * 2, i1 = mi * 2 + 1;
                if (c0 > best[i0]) { best[i0] = c0; bidx[i0] = k0; }
                if (c1 > best[i0]) { best[i0] = c1; bidx[i0] = k0 + 1; }
                if (c2 > best[i1]) { best[i1] = c2; bidx[i1] = k0; }
                if (c3 > best[i1]) { best[i1] = c3; bidx[i1] = k0 + 1; }
            }
        }
        __syncthreads();
    }

    // Cross-lane/warp argmax (scratch in dead B region; A stays live)
    float* red_s = (float*)(smem + SM_REDS);
    int*   red_i = (int*)(smem + SM_REDI);
    float* lsum  = (float*)(smem + SM_LSUM);
    const int e = warp_n * 4 + (l & 3);
    #pragma unroll
    for (int mi = 0; mi < 4; mi++) {
        #pragma unroll
        for (int h = 0; h < 2; h++) {
            int row = warp_m * 64 + mi * 16 + (l >> 2) + h * 8;
            red_s[row * 16 + e] = best[mi * 2 + h];
            red_i[row * 16 + e] = bidx[mi * 2 + h];
        }
    }
    __syncthreads();
    if (tid < TM) {
        float bs = -1e30f; int bk = 0;
        #pragma unroll
        for (int q = 0; q < 16; q++) {
            float s = red_s[tid * 16 + q];
            int   k = red_i[tid * 16 + q];
            if (s > bs || (s == bs && k < bk)) { bs = s; bk = k; }
        }
        // EXACT loss: reconstruct f_hat = hi+lo from smem A, dot with raw
        // fp32 centers (L2-resident). loss = 1 + |c|^2 - 2 * (f_norm . c)
        const float4* crow = (const float4*)(centers + (size_t)bk * D);
        const int rxor = tid & 7;
        float dot = 0.0f;
        #pragma unroll
        for (int c = 0; c < 16; c++) {
            uint4 hv = *(const uint4*)(smem + SM_A + tid * 512 + ((c ^ rxor) << 4));
            uint4 lv = *(const uint4*)(smem + SM_A + tid * 512 + (((16 + c) ^ rxor) << 4));
            float4 cv0 = crow[c * 2];
            float4 cv1 = crow[c * 2 + 1];
            dot += (bfb2f(hv.x & 0xffffu) + bfb2f(lv.x & 0xffffu)) * cv0.x;
            dot += (bfb2f(hv.x >> 16)     + bfb2f(lv.x >> 16))     * cv0.y;
            dot += (bfb2f(hv.y & 0xffffu) + bfb2f(lv.y & 0xffffu)) * cv0.z;
            dot += (bfb2f(hv.y >> 16)     + bfb2f(lv.y >> 16))     * cv0.w;
            dot += (bfb2f(hv.z & 0xffffu) + bfb2f(lv.z & 0xffffu)) * cv1.x;
            dot += (bfb2f(hv.z >> 16)     + bfb2f(lv.z >> 16))     * cv1.y;
            dot += (bfb2f(hv.w & 0xffffu) + bfb2f(lv.w & 0xffffu)) * cv1.z;
            dot += (bfb2f(hv.w >> 16)     + bfb2f(lv.w >> 16))     * cv1.w;
        }
        lsum[tid] = 1.0f + g_cnormsq[bk] - 2.0f * dot;
    }
    __syncthreads();
    #pragma unroll
    for (int s = TM / 2; s > 0; s >>= 1) {
        if (tid < s) lsum[tid] += lsum[tid + s];
        __syncthreads();
    }
    if (tid == 0) g_partial[blockIdx.x] = lsum[0];
}

// ---------------------------------------------------------------------------
// Deterministic final reduction
// ---------------------------------------------------------------------------
__global__ void finalize(float* __restrict__ out) {
    __shared__ double sd[256];
    double s = 0.0;
    for (int i = threadIdx.x; i < NBLK; i += 256) s += (double)g_partial[i];
    sd[threadIdx.x] = s;
    __syncthreads();
    for (int st = 128; st > 0; st >>= 1) {
        if (threadIdx.x < st) sd[threadIdx.x] += sd[threadIdx.x + st];
        __syncthreads();
    }
    if (threadIdx.x == 0) out[0] = (float)(sd[0] / (double)N_FEAT);
}

extern "C" void kernel_launch(void* const* d_in, const int* in_sizes, int n_in,
                              void* d_out, int out_size) {
    const float* features = (const float*)d_in[0];
    const float* centers  = (const float*)d_in[1];
    float* out = (float*)d_out;

    cudaFuncSetAttribute(gemm_argmax_mma,
                         cudaFuncAttributeMaxDynamicSharedMemorySize, SMEM_TOTAL);

    prep_centers<<<K, D>>>(centers);
    prep_features<<<N_FEAT / 8, 256>>>(features);
    gemm_argmax_mma<<<NBLK, 256, SMEM_TOTAL>>>(centers);
    finalize<<<1, 256>>>(out);
}